// round 1
// baseline (speedup 1.0000x reference)
#include <cuda_runtime.h>
#include <math.h>

#define BB 4
#define CC 64
#define NP 8192
#define OO 128
#define KNN 20

// ---------------- device scratch (static globals; no runtime alloc) ----------------
__device__ float g_xt[(size_t)BB * NP * CC];        // x transposed: [b][n][c]   (8 MB)
__device__ float g_xx[BB * NP];                     // squared norms per point
__device__ float g_uvq[(size_t)BB * NP * 256];      // [b][n][ U(64) | V(64) | Q(128) ] (33.5 MB)
__device__ int   g_idx[(size_t)BB * NP * KNN];      // top-20 neighbor indices

// ---------------- K0: transpose x (B,C,N) -> xt (B,N,C) ----------------
__global__ void k_transpose(const float* __restrict__ x) {
    __shared__ float tile[32][33];
    int b  = blockIdx.z;
    int c0 = blockIdx.y * 32;
    int n0 = blockIdx.x * 32;
    int tx = threadIdx.x, ty = threadIdx.y;   // 32 x 8
#pragma unroll
    for (int yy = 0; yy < 32; yy += 8)
        tile[ty + yy][tx] = x[((size_t)b * CC + c0 + ty + yy) * NP + n0 + tx];
    __syncthreads();
#pragma unroll
    for (int yy = 0; yy < 32; yy += 8)
        g_xt[((size_t)b * NP + n0 + ty + yy) * CC + c0 + tx] = tile[tx][ty + yy];
}

// ---------------- K0b: squared norms ----------------
__global__ void k_norm() {
    int p = blockIdx.x * blockDim.x + threadIdx.x;   // 0 .. B*N-1
    const float4* v = (const float4*)&g_xt[(size_t)p * CC];
    float s = 0.f;
#pragma unroll
    for (int i = 0; i < 16; i++) {
        float4 q = v[i];
        s += q.x * q.x + q.y * q.y + q.z * q.z + q.w * q.w;
    }
    g_xx[p] = s;
}

// ---------------- K1: precompute U, V, Q per point ----------------
// U[d]  = sum_c W1[d][c]      * xt[c]              (d < 64)
// V[d]  = sum_c (W1[d][64+c] - W1[d][c]) * xt[c]   (d < 64)
// Q[o]  = sum_c (W2[o][64+c] - W2[o][c]) * xt[c]   (o < 128)
__global__ __launch_bounds__(256) void k_uvq(const float* __restrict__ W1,
                                             const float* __restrict__ W2) {
    __shared__ float xts[16][64];
    int p0 = blockIdx.x * 16;          // flattened point base over B*N
    int o  = threadIdx.x;              // 0..255 output dim
    for (int s = threadIdx.x; s < 16 * 64; s += 256)
        xts[s >> 6][s & 63] = g_xt[(size_t)p0 * 64 + s];

    float4 wr[16];
    if (o < 64) {
        const float* r = W1 + o * 128;
#pragma unroll
        for (int i = 0; i < 16; i++)
            wr[i] = make_float4(r[4*i], r[4*i+1], r[4*i+2], r[4*i+3]);
    } else if (o < 128) {
        const float* r = W1 + (o - 64) * 128;
#pragma unroll
        for (int i = 0; i < 16; i++)
            wr[i] = make_float4(r[64+4*i]-r[4*i], r[65+4*i]-r[4*i+1],
                                r[66+4*i]-r[4*i+2], r[67+4*i]-r[4*i+3]);
    } else {
        const float* r = W2 + (o - 128) * 128;
#pragma unroll
        for (int i = 0; i < 16; i++)
            wr[i] = make_float4(r[64+4*i]-r[4*i], r[65+4*i]-r[4*i+1],
                                r[66+4*i]-r[4*i+2], r[67+4*i]-r[4*i+3]);
    }
    __syncthreads();

    float acc[16];
#pragma unroll
    for (int p = 0; p < 16; p++) acc[p] = 0.f;
#pragma unroll
    for (int c4 = 0; c4 < 16; c4++) {
        float4 w = wr[c4];
#pragma unroll
        for (int p = 0; p < 16; p++) {
            float4 xv = *(const float4*)&xts[p][c4 * 4];
            acc[p] += w.x * xv.x + w.y * xv.y + w.z * xv.z + w.w * xv.w;
        }
    }
#pragma unroll
    for (int p = 0; p < 16; p++)
        g_uvq[((size_t)p0 + p) * 256 + o] = acc[p];
}

// ---------------- K2: kNN top-20 via tiled distance GEMM ----------------
// pd(i,j) = 2*dot(xi,xj) - xx_i - xx_j ; keep top-20 per row (set semantics:
// downstream softmax-gated sum is permutation invariant over k).
__global__ __launch_bounds__(256) void k_knn() {
    __shared__ float xiT[64 * 68];      // [c][row], padded
    __shared__ float xjT[64 * 68];      // [c][col] during GEMM, then reused as D[col][row]
    __shared__ float xxi_s[64], xxj_s[64];

    int b  = blockIdx.y;
    int i0 = blockIdx.x * 64;
    int tid = threadIdx.x;

    for (int s = tid; s < 4096; s += 256) {
        int r = s >> 6, c = s & 63;
        xiT[c * 68 + r] = g_xt[((size_t)b * NP + i0 + r) * 64 + c];
    }
    if (tid < 64) xxi_s[tid] = g_xx[b * NP + i0 + tid];

    float bv[KNN]; int bi[KNN];
    float minv = -3.4e38f; int minp = 0;
#pragma unroll
    for (int t = 0; t < KNN; t++) { bv[t] = -3.4e38f; bi[t] = 0; }

    int ty = tid >> 4, tx = tid & 15;

    for (int jt = 0; jt < NP; jt += 64) {
        __syncthreads();   // previous scan done before overwriting xjT
        for (int s = tid; s < 4096; s += 256) {
            int r = s >> 6, c = s & 63;
            xjT[c * 68 + r] = g_xt[((size_t)b * NP + jt + r) * 64 + c];
        }
        if (tid < 64) xxj_s[tid] = g_xx[b * NP + jt + tid];
        __syncthreads();

        float acc[4][4];
#pragma unroll
        for (int i = 0; i < 4; i++)
#pragma unroll
            for (int j = 0; j < 4; j++) acc[i][j] = 0.f;

#pragma unroll 8
        for (int c = 0; c < 64; c++) {
            float4 a  = *(const float4*)&xiT[c * 68 + ty * 4];
            float4 bb = *(const float4*)&xjT[c * 68 + tx * 4];
            acc[0][0] += a.x * bb.x; acc[0][1] += a.x * bb.y;
            acc[0][2] += a.x * bb.z; acc[0][3] += a.x * bb.w;
            acc[1][0] += a.y * bb.x; acc[1][1] += a.y * bb.y;
            acc[1][2] += a.y * bb.z; acc[1][3] += a.y * bb.w;
            acc[2][0] += a.z * bb.x; acc[2][1] += a.z * bb.y;
            acc[2][2] += a.z * bb.z; acc[2][3] += a.z * bb.w;
            acc[3][0] += a.w * bb.x; acc[3][1] += a.w * bb.y;
            acc[3][2] += a.w * bb.z; acc[3][3] += a.w * bb.w;
        }
        __syncthreads();   // all GEMM reads of xjT done; safe to reuse as D

        float xin[4], xjn[4];
#pragma unroll
        for (int i = 0; i < 4; i++) { xin[i] = xxi_s[ty*4+i]; xjn[i] = xxj_s[tx*4+i]; }
#pragma unroll
        for (int i = 0; i < 4; i++)
#pragma unroll
            for (int j = 0; j < 4; j++)
                xjT[(tx * 4 + j) * 68 + (ty * 4 + i)] = 2.f * acc[i][j] - xin[i] - xjn[j];
        __syncthreads();

        if (tid < 64) {
#pragma unroll 4
            for (int j = 0; j < 64; j++) {
                float v = xjT[j * 68 + tid];
                if (v > minv) {
                    bv[minp] = v; bi[minp] = jt + j;
                    minv = bv[0]; minp = 0;
#pragma unroll
                    for (int t = 1; t < KNN; t++)
                        if (bv[t] < minv) { minv = bv[t]; minp = t; }
                }
            }
        }
    }
    if (tid < 64) {
#pragma unroll
        for (int t = 0; t < KNN; t++)
            g_idx[((size_t)b * NP + i0 + tid) * KNN + t] = bi[t];
    }
}

// ---------------- K3: fused gather + softmax gate + output GEMM ----------------
// t[c] = (sum_k nbr_k[c]*e_k)/sum_k e_k ;  out[o] = Q[o] + sum_{c<64} W2[o][c]*t[c]
__global__ __launch_bounds__(256) void k_fuse(const float* __restrict__ W2,
                                              float* __restrict__ out) {
    __shared__ float w2as[64 * 128];     // W2a transposed: [c][o]
    __shared__ float t_s[16][64];
    __shared__ int   idxs[16][KNN];

    int blk = blockIdx.x;                // 2048 blocks
    int b   = blk >> 9;                  // 512 blocks per batch
    int n0  = (blk & 511) * 16;
    int tid = threadIdx.x;
    size_t base = (size_t)b * NP;

    for (int s = tid; s < 8192; s += 256) {
        int o = s >> 6, c = s & 63;      // read W2 coalesced over c
        w2as[c * 128 + o] = W2[o * 128 + c];
    }
    for (int s = tid; s < 16 * KNN; s += 256)
        idxs[s / KNN][s % KNN] = g_idx[(base + n0) * KNN + s];
    __syncthreads();

    // Phase A: gates + gated neighbor sums (4 points per pass, 64 dims each)
    for (int pass = 0; pass < 4; pass++) {
        int pt = pass * 4 + (tid >> 6);
        int d  = tid & 63;
        float vv = g_uvq[(base + n0 + pt) * 256 + 64 + d];
        float h[KNN];
#pragma unroll
        for (int k = 0; k < KNN; k++) {
            int j = idxs[pt][k];
            h[k] = g_uvq[(base + j) * 256 + d] + vv;
        }
        float m = h[0];
#pragma unroll
        for (int k = 1; k < KNN; k++) m = fmaxf(m, h[k]);
        float S = 0.f, ws = 0.f;
#pragma unroll
        for (int k = 0; k < KNN; k++) {
            float e = __expf(h[k] - m);
            S += e;
            int j = idxs[pt][k];
            ws += g_xt[(base + j) * 64 + d] * e;
        }
        t_s[pt][d] = ws / S;
    }
    __syncthreads();

    // Phase B: out[o] = Q[o] + W2a . t   (8 points per thread-group)
    int o = tid & 127, g = tid >> 7;
    float acc[8];
#pragma unroll
    for (int p = 0; p < 8; p++)
        acc[p] = g_uvq[(base + n0 + g * 8 + p) * 256 + 128 + o];
#pragma unroll 8
    for (int c = 0; c < 64; c++) {
        float w = w2as[c * 128 + o];
#pragma unroll
        for (int p = 0; p < 8; p++) acc[p] += w * t_s[g * 8 + p][c];
    }
    float* op = out + ((size_t)b * OO + o) * NP + n0 + g * 8;
    *(float4*)op       = make_float4(acc[0], acc[1], acc[2], acc[3]);
    *(float4*)(op + 4) = make_float4(acc[4], acc[5], acc[6], acc[7]);
}

// ---------------- launch ----------------
extern "C" void kernel_launch(void* const* d_in, const int* in_sizes, int n_in,
                              void* d_out, int out_size) {
    const float* x  = (const float*)d_in[0];
    const float* W1 = (const float*)d_in[1];
    const float* W2 = (const float*)d_in[2];
    float* out = (float*)d_out;

    k_transpose<<<dim3(NP / 32, CC / 32, BB), dim3(32, 8)>>>(x);
    k_norm<<<(BB * NP) / 256, 256>>>();
    k_uvq<<<(BB * NP) / 16, 256>>>(W1, W2);
    k_knn<<<dim3(NP / 64, BB), 256>>>();
    k_fuse<<<(BB * NP) / 16, 256>>>(W2, out);
}